// round 5
// baseline (speedup 1.0000x reference)
#include <cuda_runtime.h>

#define BATCH 8
#define NPTS  4096
#define MPTS  2048
#define FDIM  64
#define KNBR  64
#define NG    (BATCH*MPTS)
#define CAP   256

// output segments (float32): x_out [NG,128] | pos_out [NG,3] | batch_out [NG]
#define XSEG   (NG*128)
#define PBASE  XSEG
#define BBASE  (XSEG + NG*3)
#define TOTSEG (BBASE + NG)

__device__ float g_q[NG*3];
__device__ int   g_nbr[NG*KNBR];
__device__ int   g_cnt[NG];

typedef unsigned long long u64;

__device__ __forceinline__ u64 pk2(float lo, float hi) {
    u64 r; asm("mov.b64 %0, {%1, %2};" : "=l"(r) : "f"(lo), "f"(hi)); return r;
}
__device__ __forceinline__ void up2(u64 v, float& lo, float& hi) {
    asm("mov.b64 {%0, %1}, %2;" : "=f"(lo), "=f"(hi) : "l"(v));
}
__device__ __forceinline__ u64 add2(u64 a, u64 b) {
    u64 r; asm("add.rn.f32x2 %0, %1, %2;" : "=l"(r) : "l"(a), "l"(b)); return r;
}
__device__ __forceinline__ u64 mul2(u64 a, u64 b) {
    u64 r; asm("mul.rn.f32x2 %0, %1, %2;" : "=l"(r) : "l"(a), "l"(b)); return r;
}
__device__ __forceinline__ u64 fma2(u64 a, u64 b, u64 c) {
    u64 r; asm("fma.rn.f32x2 %0, %1, %2, %3;" : "=l"(r) : "l"(a), "l"(b), "l"(c)); return r;
}

// ============================================================================
// 1) FPS: one block/cloud, 512 threads, 8 pts/thread as 4 f32x2 pairs.
//    Per-half arithmetic identical to scalar rn ops -> bit-exact vs reference.
// ============================================================================
__global__ void __launch_bounds__(512)
fps_kernel(const float* __restrict__ pos, float* __restrict__ dout, int out_size)
{
    extern __shared__ float sp[];              // [NPTS*4]
    __shared__ float rd[16];
    __shared__ int   ri[16];
    __shared__ int   s_cur;

    const int b = blockIdx.x, tid = threadIdx.x;
    const int lane = tid & 31, w = tid >> 5;
    const float* pb = pos + (size_t)b * NPTS * 3;

    for (int i = tid; i < NPTS * 3; i += 512) {
        int p = i / 3, c = i - 3 * p;
        sp[4 * p + c] = pb[i];
    }
    if (tid == 0) s_cur = 0;
    __syncthreads();

    u64 px2[4], py2[4], pz2[4];
    float mdA[4], mdB[4];
    const float4* sp4 = (const float4*)sp;
#pragma unroll
    for (int p = 0; p < 4; p++) {
        float4 A = sp4[1024 * p + tid];
        float4 Bq = sp4[1024 * p + 512 + tid];
        px2[p] = pk2(A.x, Bq.x);
        py2[p] = pk2(A.y, Bq.y);
        pz2[p] = pk2(A.z, Bq.z);
        mdA[p] = __int_as_float(0x7f800000);
        mdB[p] = __int_as_float(0x7f800000);
    }

    if (tid == 0) {
        int g = b * MPTS;
        g_q[3*g] = sp[0]; g_q[3*g+1] = sp[1]; g_q[3*g+2] = sp[2];
        if (out_size >= BBASE) {
            dout[PBASE+3*g] = sp[0]; dout[PBASE+3*g+1] = sp[1]; dout[PBASE+3*g+2] = sp[2];
        }
        if (out_size >= TOTSEG) dout[BBASE+g] = (float)b;
    }
    __syncthreads();

    for (int step = 1; step < MPTS; step++) {
        float4 L = sp4[s_cur];
        u64 nx = pk2(-L.x, -L.x);
        u64 ny = pk2(-L.y, -L.y);
        u64 nz = pk2(-L.z, -L.z);
        float bd = -1.0f; int bi = 0;
#pragma unroll
        for (int p = 0; p < 4; p++) {
            u64 dx = add2(px2[p], nx);
            u64 dy = add2(py2[p], ny);
            u64 dz = add2(pz2[p], nz);
            u64 s  = add2(add2(mul2(dx, dx), mul2(dy, dy)), mul2(dz, dz));
            float dA, dB; up2(s, dA, dB);
            float mA = fminf(mdA[p], dA); mdA[p] = mA;
            if (mA > bd) { bd = mA; bi = 1024 * p + tid; }
            float mB = fminf(mdB[p], dB); mdB[p] = mB;
            if (mB > bd) { bd = mB; bi = 1024 * p + 512 + tid; }
        }
#pragma unroll
        for (int off = 16; off >= 1; off >>= 1) {
            float od = __shfl_down_sync(0xffffffffu, bd, off);
            int   oi = __shfl_down_sync(0xffffffffu, bi, off);
            if (od > bd || (od == bd && oi < bi)) { bd = od; bi = oi; }
        }
        if (lane == 0) { rd[w] = bd; ri[w] = bi; }
        __syncthreads();
        if (w == 0) {
            float d2 = (lane < 16) ? rd[lane] : -2.0f;
            int   i2 = (lane < 16) ? ri[lane] : 0x7fffffff;
#pragma unroll
            for (int off = 8; off >= 1; off >>= 1) {
                float od = __shfl_down_sync(0xffffffffu, d2, off);
                int   oi = __shfl_down_sync(0xffffffffu, i2, off);
                if (od > d2 || (od == d2 && oi < i2)) { d2 = od; i2 = oi; }
            }
            if (lane == 0) {
                s_cur = i2;
                int g = b * MPTS + step;
                float qx = sp[4*i2], qy = sp[4*i2+1], qz = sp[4*i2+2];
                g_q[3*g] = qx; g_q[3*g+1] = qy; g_q[3*g+2] = qz;
                if (out_size >= BBASE) {
                    dout[PBASE+3*g] = qx; dout[PBASE+3*g+1] = qy; dout[PBASE+3*g+2] = qz;
                }
                if (out_size >= TOTSEG) dout[BBASE+g] = (float)b;
            }
        }
        __syncthreads();
    }
}

// ============================================================================
// 2) Radius + 64 nearest (stable top_k order). One warp per centroid.
// ============================================================================
__global__ void __launch_bounds__(256)
nbr_kernel(const float* __restrict__ pos)
{
    extern __shared__ float sm2[];             // sp[NPTS*4] | bufd[8*CAP] | bufi[8*CAP]
    float* sp = sm2;
    const int tid = threadIdx.x, lane = tid & 31, w = tid >> 5;
    const int g = blockIdx.x * 8 + w;
    const int b = (blockIdx.x * 8) / MPTS;
    const float* pb = pos + (size_t)b * NPTS * 3;

    for (int i = tid; i < NPTS * 3; i += 256) {
        int p = i / 3, c = i - 3 * p;
        sp[4 * p + c] = pb[i];
    }
    __syncthreads();

    float* bufd = sm2 + 4 * NPTS + w * CAP;
    int*   bufi = (int*)(sm2 + 4 * NPTS + 8 * CAP) + w * CAP;

    const float qx = g_q[3*g], qy = g_q[3*g+1], qz = g_q[3*g+2];
    const float R2 = (float)(0.15 * 0.15);
    const float4* sp4 = (const float4*)sp;

    int cnt = 0;
    for (int i = lane; i < NPTS; i += 32) {
        float4 p = sp4[i];
        float dx = __fadd_rn(qx, -p.x);
        float dy = __fadd_rn(qy, -p.y);
        float dz = __fadd_rn(qz, -p.z);
        float d2 = __fadd_rn(__fadd_rn(__fmul_rn(dx,dx), __fmul_rn(dy,dy)),
                             __fmul_rn(dz,dz));
        bool keep = (d2 <= R2);
        unsigned msk = __ballot_sync(0xffffffffu, keep);
        if (keep) {
            int ofs = cnt + __popc(msk & ((1u << lane) - 1u));
            if (ofs < CAP) { bufd[ofs] = d2; bufi[ofs] = i; }
        }
        cnt += __popc(msk);
    }
    if (cnt > CAP) cnt = CAP;

    if (cnt <= KNBR) {
        for (int t = lane; t < cnt; t += 32) g_nbr[g*KNBR + t] = bufi[t];
        if (lane == 0) g_cnt[g] = cnt;
    } else {
        for (int t = lane; t < cnt; t += 32) {
            float di = bufd[t]; int ii = bufi[t];
            int r = 0;
            for (int j = 0; j < cnt; j++) {
                float dj = bufd[j];
                r += (int)((dj < di) | ((dj == di) & (bufi[j] < ii)));
            }
            if (r < KNBR) g_nbr[g*KNBR + r] = ii;
        }
        if (lane == 0) g_cnt[g] = KNBR;
    }
}

// ============================================================================
// 3) MLP (67->64->64->128, ReLU) + max. f32x2 row-pair packing, transposed
//    activations, duplicated weights in smem, double-buffered feat gather.
// smem (floats):
// ============================================================================
#define OW1D 0          // 67x128 dup  = 8576
#define OW2D 8576       // 64x128 dup  = 8192
#define OW3D 16768      // 64x256 dup  = 16384
#define OB1  33152      // 64
#define OB2  33216      // 64
#define OB3  33280      // 128
#define OF0  33408      // featT 68x66 = 4488
#define OF1  37896      // featT 68x66 = 4488
#define OH1  42384      // h1T 64x66   = 4224
#define OH2  46608      // h2T 64x66   = 4224
#define ORD  50832      // red 16x128  = 2048
#define MLP_SM 52880    // floats

__device__ __forceinline__ void pf_load(
    const float* __restrict__ x, const float* __restrict__ pos,
    int g, int e, int part, float v[16], float3& pp, float3& qq)
{
    int cnt = g_cnt[g];
    int j = g_nbr[g * KNBR + ((e < cnt) ? e : 0)];
    int b = g / MPTS;
    const float* xr = x + ((size_t)b * NPTS + j) * FDIM;
#pragma unroll
    for (int i = 0; i < 16; i++) v[i] = xr[part + 4 * i];
    if (part == 0) {
        const float* pr = pos + ((size_t)b * NPTS + j) * 3;
        pp.x = pr[0]; pp.y = pr[1]; pp.z = pr[2];
        qq.x = g_q[3*g]; qq.y = g_q[3*g+1]; qq.z = g_q[3*g+2];
    }
}

__device__ __forceinline__ void pf_store(
    float* buf, int e, int part, const float v[16], float3 pp, float3 qq)
{
#pragma unroll
    for (int i = 0; i < 16; i++) buf[(part + 4 * i) * 66 + e] = v[i];
    if (part == 0) {
        buf[64 * 66 + e] = __fadd_rn(pp.x, -qq.x);
        buf[65 * 66 + e] = __fadd_rn(pp.y, -qq.y);
        buf[66 * 66 + e] = __fadd_rn(pp.z, -qq.z);
    }
}

__global__ void __launch_bounds__(256)
mlp_kernel(const float* __restrict__ x, const float* __restrict__ pos,
           const float* __restrict__ W1, const float* __restrict__ b1,
           const float* __restrict__ W2, const float* __restrict__ b2,
           const float* __restrict__ W3, const float* __restrict__ b3,
           float* __restrict__ dout, int out_size)
{
    extern __shared__ float sm[];
    const int tid = threadIdx.x;

    // stage weights, duplicated (w,w) pairs
    for (int idx = tid; idx < 67 * 64; idx += 256) {
        int k = idx >> 6, c = idx & 63;
        float w = W1[idx];
        *(float2*)(sm + OW1D + k * 128 + 2 * c) = make_float2(w, w);
    }
    for (int idx = tid; idx < 64 * 64; idx += 256) {
        int k = idx >> 6, c = idx & 63;
        float w = W2[idx];
        *(float2*)(sm + OW2D + k * 128 + 2 * c) = make_float2(w, w);
    }
    for (int idx = tid; idx < 64 * 128; idx += 256) {
        int k = idx >> 7, c = idx & 127;
        float w = W3[idx];
        *(float2*)(sm + OW3D + k * 256 + 2 * c) = make_float2(w, w);
    }
    if (tid < 64)  { sm[OB1 + tid] = b1[tid]; sm[OB2 + tid] = b2[tid]; }
    if (tid < 128)   sm[OB3 + tid] = b3[tid];

    const int rg = tid >> 4;   // 0..15: rows 4rg..4rg+3
    const int cg = tid & 15;   // 0..15
    const int e = tid >> 2, part = tid & 3;
    const int base = blockIdx.x * 8;

    float v[16]; float3 pp, qq;
    pf_load(x, pos, base, e, part, v, pp, qq);
    pf_store(sm + OF0, e, part, v, pp, qq);
    __syncthreads();

    for (int ci = 0; ci < 8; ci++) {
        const int g = base + ci;
        const float* buf = sm + ((ci & 1) ? OF1 : OF0);

        float nv[16]; float3 npp, nqq;
        if (ci < 7) pf_load(x, pos, g + 1, e, part, nv, npp, nqq);

        // ---- layer 1: featT[67][64] x W1[67][64] -> h1T[64][64]
        {
            u64 acc[2][4];
#pragma unroll
            for (int c = 0; c < 4; c++) {
                float bb = sm[OB1 + 4 * cg + c];
                acc[0][c] = pk2(bb, bb);
                acc[1][c] = pk2(bb, bb);
            }
#pragma unroll 4
            for (int k = 0; k < 67; k++) {
                const u64* aT = (const u64*)(buf + k * 66 + 4 * rg);
                u64 a0 = aT[0], a1 = aT[1];
                const u64* wd = (const u64*)(sm + OW1D + k * 128 + 8 * cg);
                u64 w0 = wd[0], w1 = wd[1], w2 = wd[2], w3 = wd[3];
                acc[0][0] = fma2(a0, w0, acc[0][0]);
                acc[0][1] = fma2(a0, w1, acc[0][1]);
                acc[0][2] = fma2(a0, w2, acc[0][2]);
                acc[0][3] = fma2(a0, w3, acc[0][3]);
                acc[1][0] = fma2(a1, w0, acc[1][0]);
                acc[1][1] = fma2(a1, w1, acc[1][1]);
                acc[1][2] = fma2(a1, w2, acc[1][2]);
                acc[1][3] = fma2(a1, w3, acc[1][3]);
            }
#pragma unroll
            for (int p = 0; p < 2; p++)
#pragma unroll
                for (int c = 0; c < 4; c++) {
                    float lo, hi; up2(acc[p][c], lo, hi);
                    float* hp = sm + OH1 + (4 * cg + c) * 66 + 4 * rg + 2 * p;
                    hp[0] = fmaxf(lo, 0.0f);
                    hp[1] = fmaxf(hi, 0.0f);
                }
        }
        __syncthreads();

        // ---- layer 2
        {
            u64 acc[2][4];
#pragma unroll
            for (int c = 0; c < 4; c++) {
                float bb = sm[OB2 + 4 * cg + c];
                acc[0][c] = pk2(bb, bb);
                acc[1][c] = pk2(bb, bb);
            }
#pragma unroll 4
            for (int k = 0; k < 64; k++) {
                const u64* aT = (const u64*)(sm + OH1 + k * 66 + 4 * rg);
                u64 a0 = aT[0], a1 = aT[1];
                const u64* wd = (const u64*)(sm + OW2D + k * 128 + 8 * cg);
                u64 w0 = wd[0], w1 = wd[1], w2 = wd[2], w3 = wd[3];
                acc[0][0] = fma2(a0, w0, acc[0][0]);
                acc[0][1] = fma2(a0, w1, acc[0][1]);
                acc[0][2] = fma2(a0, w2, acc[0][2]);
                acc[0][3] = fma2(a0, w3, acc[0][3]);
                acc[1][0] = fma2(a1, w0, acc[1][0]);
                acc[1][1] = fma2(a1, w1, acc[1][1]);
                acc[1][2] = fma2(a1, w2, acc[1][2]);
                acc[1][3] = fma2(a1, w3, acc[1][3]);
            }
#pragma unroll
            for (int p = 0; p < 2; p++)
#pragma unroll
                for (int c = 0; c < 4; c++) {
                    float lo, hi; up2(acc[p][c], lo, hi);
                    float* hp = sm + OH2 + (4 * cg + c) * 66 + 4 * rg + 2 * p;
                    hp[0] = fmaxf(lo, 0.0f);
                    hp[1] = fmaxf(hi, 0.0f);
                }
        }
        __syncthreads();

        // ---- layer 3: cols 8cg..8cg+7, relu + max over 4 rows -> red
        {
            u64 acc[2][8];
#pragma unroll
            for (int c = 0; c < 8; c++) {
                float bb = sm[OB3 + 8 * cg + c];
                acc[0][c] = pk2(bb, bb);
                acc[1][c] = pk2(bb, bb);
            }
#pragma unroll 2
            for (int k = 0; k < 64; k++) {
                const u64* aT = (const u64*)(sm + OH2 + k * 66 + 4 * rg);
                u64 a0 = aT[0], a1 = aT[1];
                const u64* wd = (const u64*)(sm + OW3D + k * 256 + 16 * cg);
#pragma unroll
                for (int c = 0; c < 8; c++) {
                    u64 w = wd[c];
                    acc[0][c] = fma2(a0, w, acc[0][c]);
                    acc[1][c] = fma2(a1, w, acc[1][c]);
                }
            }
#pragma unroll
            for (int c = 0; c < 8; c++) {
                float l0, h0, l1, h1;
                up2(acc[0][c], l0, h0);
                up2(acc[1][c], l1, h1);
                float m = fmaxf(fmaxf(fmaxf(l0, h0), fmaxf(l1, h1)), 0.0f);
                sm[ORD + rg * 128 + 8 * cg + c] = m;
            }
        }
        __syncthreads();

        if (tid < 128) {
            float m = sm[ORD + tid];
#pragma unroll
            for (int r = 1; r < 16; r++) m = fmaxf(m, sm[ORD + r * 128 + tid]);
            dout[(size_t)g * 128 + tid] = m;
        }

        if (ci < 7) pf_store(sm + ((ci & 1) ? OF0 : OF1), e, part, nv, npp, nqq);
        __syncthreads();
    }
}

// ============================================================================
extern "C" void kernel_launch(void* const* d_in, const int* in_sizes, int n_in,
                              void* d_out, int out_size)
{
    const float* x   = (const float*)d_in[0];
    const float* pos = (const float*)d_in[1];
    const float* W1 = (const float*)d_in[3];
    const float* b1 = (const float*)d_in[4];
    const float* W2 = (const float*)d_in[5];
    const float* b2 = (const float*)d_in[6];
    const float* W3 = (const float*)d_in[7];
    const float* b3 = (const float*)d_in[8];
    float* out = (float*)d_out;

    const int fps_smem = NPTS * 4 * sizeof(float);                 // 64 KB
    const int nbr_smem = fps_smem + 8 * CAP * 2 * sizeof(float);   // 80 KB
    const int mlp_smem = MLP_SM * sizeof(float);                   // ~207 KB
    cudaFuncSetAttribute(fps_kernel, cudaFuncAttributeMaxDynamicSharedMemorySize, fps_smem);
    cudaFuncSetAttribute(nbr_kernel, cudaFuncAttributeMaxDynamicSharedMemorySize, nbr_smem);
    cudaFuncSetAttribute(mlp_kernel, cudaFuncAttributeMaxDynamicSharedMemorySize, mlp_smem);

    fps_kernel<<<BATCH, 512, fps_smem>>>(pos, out, out_size);
    nbr_kernel<<<NG / 8, 256, nbr_smem>>>(pos);
    mlp_kernel<<<NG / 8, 256, mlp_smem>>>(x, pos, W1, b1, W2, b2, W3, b3, out, out_size);
}

// round 6
// speedup vs baseline: 1.5481x; 1.5481x over previous
#include <cuda_runtime.h>

#define BATCH 8
#define NPTS  4096
#define MPTS  2048
#define FDIM  64
#define KNBR  64
#define NG    (BATCH*MPTS)
#define CAP   256

// output segments (float32): x_out [NG,128] | pos_out [NG,3] | batch_out [NG]
#define XSEG   (NG*128)
#define PBASE  XSEG
#define BBASE  (XSEG + NG*3)
#define TOTSEG (BBASE + NG)

__device__ float g_q[NG*3];
__device__ int   g_nbr[NG*KNBR];
__device__ int   g_cnt[NG];

// ============================================================================
// 1) Farthest point sampling: one block per cloud, 512 threads, 8 pts/thread
//    in registers. Scalar rn math, op order identical to reference.
// ============================================================================
__global__ void __launch_bounds__(512)
fps_kernel(const float* __restrict__ pos, float* __restrict__ dout, int out_size)
{
    extern __shared__ float sp[];              // [NPTS*4]
    __shared__ float rd[16];
    __shared__ int   ri[16];
    __shared__ int   s_cur;

    const int b = blockIdx.x, tid = threadIdx.x;
    const int lane = tid & 31, w = tid >> 5;
    const float* pb = pos + (size_t)b * NPTS * 3;

    for (int i = tid; i < NPTS * 3; i += 512) {
        int p = i / 3, c = i - 3 * p;
        sp[4 * p + c] = pb[i];
    }
    if (tid == 0) s_cur = 0;
    __syncthreads();

    float px[8], py[8], pz[8], md[8];
#pragma unroll
    for (int j = 0; j < 8; j++) {
        int idx = j * 512 + tid;
        px[j] = sp[4 * idx]; py[j] = sp[4 * idx + 1]; pz[j] = sp[4 * idx + 2];
        md[j] = __int_as_float(0x7f800000);
    }

    if (tid == 0) {
        int g = b * MPTS;
        g_q[3*g] = sp[0]; g_q[3*g+1] = sp[1]; g_q[3*g+2] = sp[2];
        if (out_size >= BBASE) {
            dout[PBASE+3*g] = sp[0]; dout[PBASE+3*g+1] = sp[1]; dout[PBASE+3*g+2] = sp[2];
        }
        if (out_size >= TOTSEG) dout[BBASE+g] = (float)b;
    }

    const float4* sp4 = (const float4*)sp;

    for (int step = 1; step < MPTS; step++) {
        float4 L = sp4[s_cur];
        float bd = -1.0f; int bi = 0;
#pragma unroll
        for (int j = 0; j < 8; j++) {
            float dx = __fadd_rn(px[j], -L.x);
            float dy = __fadd_rn(py[j], -L.y);
            float dz = __fadd_rn(pz[j], -L.z);
            float d  = __fadd_rn(__fadd_rn(__fmul_rn(dx,dx), __fmul_rn(dy,dy)),
                                 __fmul_rn(dz,dz));
            float m = fminf(md[j], d);
            md[j] = m;
            if (m > bd) { bd = m; bi = j * 512 + tid; }
        }
#pragma unroll
        for (int off = 16; off >= 1; off >>= 1) {
            float od = __shfl_down_sync(0xffffffffu, bd, off);
            int   oi = __shfl_down_sync(0xffffffffu, bi, off);
            if (od > bd || (od == bd && oi < bi)) { bd = od; bi = oi; }
        }
        if (lane == 0) { rd[w] = bd; ri[w] = bi; }
        __syncthreads();
        if (w == 0) {
            float d2 = (lane < 16) ? rd[lane] : -2.0f;
            int   i2 = (lane < 16) ? ri[lane] : 0x7fffffff;
#pragma unroll
            for (int off = 8; off >= 1; off >>= 1) {
                float od = __shfl_down_sync(0xffffffffu, d2, off);
                int   oi = __shfl_down_sync(0xffffffffu, i2, off);
                if (od > d2 || (od == d2 && oi < i2)) { d2 = od; i2 = oi; }
            }
            if (lane == 0) {
                s_cur = i2;
                int g = b * MPTS + step;
                float qx = sp[4*i2], qy = sp[4*i2+1], qz = sp[4*i2+2];
                g_q[3*g] = qx; g_q[3*g+1] = qy; g_q[3*g+2] = qz;
                if (out_size >= BBASE) {
                    dout[PBASE+3*g] = qx; dout[PBASE+3*g+1] = qy; dout[PBASE+3*g+2] = qz;
                }
                if (out_size >= TOTSEG) dout[BBASE+g] = (float)b;
            }
        }
        __syncthreads();
    }
}

// ============================================================================
// 2) Radius + 64 nearest (stable top_k order). One warp per centroid.
// ============================================================================
__global__ void __launch_bounds__(256)
nbr_kernel(const float* __restrict__ pos)
{
    extern __shared__ float sm2[];             // sp[NPTS*4] | bufd[8*CAP] | bufi[8*CAP]
    float* sp = sm2;
    const int tid = threadIdx.x, lane = tid & 31, w = tid >> 5;
    const int g = blockIdx.x * 8 + w;
    const int b = (blockIdx.x * 8) / MPTS;
    const float* pb = pos + (size_t)b * NPTS * 3;

    for (int i = tid; i < NPTS * 3; i += 256) {
        int p = i / 3, c = i - 3 * p;
        sp[4 * p + c] = pb[i];
    }
    __syncthreads();

    float* bufd = sm2 + 4 * NPTS + w * CAP;
    int*   bufi = (int*)(sm2 + 4 * NPTS + 8 * CAP) + w * CAP;

    const float qx = g_q[3*g], qy = g_q[3*g+1], qz = g_q[3*g+2];
    const float R2 = (float)(0.15 * 0.15);
    const float4* sp4 = (const float4*)sp;

    int cnt = 0;
    for (int i = lane; i < NPTS; i += 32) {
        float4 p = sp4[i];
        float dx = __fadd_rn(qx, -p.x);
        float dy = __fadd_rn(qy, -p.y);
        float dz = __fadd_rn(qz, -p.z);
        float d2 = __fadd_rn(__fadd_rn(__fmul_rn(dx,dx), __fmul_rn(dy,dy)),
                             __fmul_rn(dz,dz));
        bool keep = (d2 <= R2);
        unsigned msk = __ballot_sync(0xffffffffu, keep);
        if (keep) {
            int ofs = cnt + __popc(msk & ((1u << lane) - 1u));
            if (ofs < CAP) { bufd[ofs] = d2; bufi[ofs] = i; }
        }
        cnt += __popc(msk);
    }
    if (cnt > CAP) cnt = CAP;

    if (cnt <= KNBR) {
        for (int t = lane; t < cnt; t += 32) g_nbr[g*KNBR + t] = bufi[t];
        if (lane == 0) g_cnt[g] = cnt;
    } else {
        for (int t = lane; t < cnt; t += 32) {
            float di = bufd[t]; int ii = bufi[t];
            int r = 0;
            for (int j = 0; j < cnt; j++) {
                float dj = bufd[j];
                r += (int)((dj < di) | ((dj == di) & (bufi[j] < ii)));
            }
            if (r < KNBR) g_nbr[g*KNBR + r] = ii;
        }
        if (lane == 0) g_cnt[g] = KNBR;
    }
}

// ============================================================================
// 3) MLP (67->64->64->128, ReLU) + max over neighbors. R3 register tiling,
//    plus: vectorized (LDG.128) feat gather, double-buffered across centroids.
// smem floats:
//   W1 4288 | b1 64 | W2 4096 | b2 64 | W3 8192 | b3 128 |
//   feat0 64x68 | feat1 64x68 | h1 64x65 | h2 64x65 | red 16x128
// ============================================================================
#define SM_W1 0
#define SM_B1 4288
#define SM_W2 4352
#define SM_B2 8448
#define SM_W3 8512
#define SM_B3 16704
#define SM_F0 16832
#define SM_F1 21184
#define SM_H1 25536
#define SM_H2 29696
#define SM_R  33856
#define SM_TOT 35904

// gather: e = tid>>2 (row 0..63), sub = tid&3 loads 4 float4s of x row;
// sub==0 also computes pos_j - q.
__device__ __forceinline__ void gload(
    const float* __restrict__ x, const float* __restrict__ pos,
    int g, int e, int sub, float4 v[4], float3& dp)
{
    int cnt = g_cnt[g];
    int j = g_nbr[g * KNBR + ((e < cnt) ? e : 0)];
    int b = g / MPTS;
    const float4* xr = (const float4*)(x + ((size_t)b * NPTS + j) * FDIM);
#pragma unroll
    for (int i = 0; i < 4; i++) v[i] = xr[sub * 4 + i];
    if (sub == 0) {
        const float* pr = pos + ((size_t)b * NPTS + j) * 3;
        dp.x = __fadd_rn(pr[0], -g_q[3*g]);
        dp.y = __fadd_rn(pr[1], -g_q[3*g+1]);
        dp.z = __fadd_rn(pr[2], -g_q[3*g+2]);
    }
}

__device__ __forceinline__ void gstore(
    float* buf, int e, int sub, const float4 v[4], float3 dp)
{
    float4* dst = (float4*)(buf + e * 68 + sub * 16);
#pragma unroll
    for (int i = 0; i < 4; i++) dst[i] = v[i];
    if (sub == 0) {
        buf[e * 68 + 64] = dp.x;
        buf[e * 68 + 65] = dp.y;
        buf[e * 68 + 66] = dp.z;
    }
}

__global__ void __launch_bounds__(256)
mlp_kernel(const float* __restrict__ x, const float* __restrict__ pos,
           const float* __restrict__ W1, const float* __restrict__ b1,
           const float* __restrict__ W2, const float* __restrict__ b2,
           const float* __restrict__ W3, const float* __restrict__ b3,
           float* __restrict__ dout, int out_size)
{
    extern __shared__ float sm[];
    const int tid = threadIdx.x;
    for (int i = tid; i < 4288; i += 256) sm[SM_W1 + i] = W1[i];
    for (int i = tid; i < 4096; i += 256) sm[SM_W2 + i] = W2[i];
    for (int i = tid; i < 8192; i += 256) sm[SM_W3 + i] = W3[i];
    if (tid < 64)  { sm[SM_B1 + tid] = b1[tid]; sm[SM_B2 + tid] = b2[tid]; }
    if (tid < 128)   sm[SM_B3 + tid] = b3[tid];

    const int rg = tid >> 4;    // 0..15: rows 4rg..4rg+3 (neighbors)
    const int cg = tid & 15;    // 0..15: col group
    const int e = tid >> 2, sub = tid & 3;
    const int base = blockIdx.x * 8;

    float4 v[4]; float3 dp;
    gload(x, pos, base, e, sub, v, dp);
    gstore(sm + SM_F0, e, sub, v, dp);
    __syncthreads();

    for (int ci = 0; ci < 8; ci++) {
        const int g = base + ci;
        const float* feat = sm + ((ci & 1) ? SM_F1 : SM_F0);

        float4 nv[4]; float3 ndp;
        if (ci < 7) gload(x, pos, g + 1, e, sub, nv, ndp);

        // layer 1: [64x67]@[67x64]
        {
            float acc[4][4];
#pragma unroll
            for (int i = 0; i < 4; i++)
#pragma unroll
                for (int c = 0; c < 4; c++) acc[i][c] = sm[SM_B1 + 4*cg + c];
            for (int k = 0; k < 67; k++) {
                float4 wv = *(const float4*)(sm + SM_W1 + k*64 + 4*cg);
#pragma unroll
                for (int i = 0; i < 4; i++) {
                    float a = feat[(4*rg + i)*68 + k];
                    acc[i][0] = fmaf(a, wv.x, acc[i][0]);
                    acc[i][1] = fmaf(a, wv.y, acc[i][1]);
                    acc[i][2] = fmaf(a, wv.z, acc[i][2]);
                    acc[i][3] = fmaf(a, wv.w, acc[i][3]);
                }
            }
#pragma unroll
            for (int i = 0; i < 4; i++)
#pragma unroll
                for (int c = 0; c < 4; c++)
                    sm[SM_H1 + (4*rg + i)*65 + 4*cg + c] = fmaxf(acc[i][c], 0.0f);
        }
        __syncthreads();

        // layer 2: [64x64]@[64x64]
        {
            float acc[4][4];
#pragma unroll
            for (int i = 0; i < 4; i++)
#pragma unroll
                for (int c = 0; c < 4; c++) acc[i][c] = sm[SM_B2 + 4*cg + c];
            for (int k = 0; k < 64; k++) {
                float4 wv = *(const float4*)(sm + SM_W2 + k*64 + 4*cg);
#pragma unroll
                for (int i = 0; i < 4; i++) {
                    float a = sm[SM_H1 + (4*rg + i)*65 + k];
                    acc[i][0] = fmaf(a, wv.x, acc[i][0]);
                    acc[i][1] = fmaf(a, wv.y, acc[i][1]);
                    acc[i][2] = fmaf(a, wv.z, acc[i][2]);
                    acc[i][3] = fmaf(a, wv.w, acc[i][3]);
                }
            }
#pragma unroll
            for (int i = 0; i < 4; i++)
#pragma unroll
                for (int c = 0; c < 4; c++)
                    sm[SM_H2 + (4*rg + i)*65 + 4*cg + c] = fmaxf(acc[i][c], 0.0f);
        }
        __syncthreads();

        // layer 3: [64x64]@[64x128], relu + max over own 4 rows
        {
            float acc[4][8];
#pragma unroll
            for (int i = 0; i < 4; i++)
#pragma unroll
                for (int c = 0; c < 8; c++) acc[i][c] = sm[SM_B3 + 8*cg + c];
            for (int k = 0; k < 64; k++) {
                float4 w0 = *(const float4*)(sm + SM_W3 + k*128 + 8*cg);
                float4 w1 = *(const float4*)(sm + SM_W3 + k*128 + 8*cg + 4);
#pragma unroll
                for (int i = 0; i < 4; i++) {
                    float a = sm[SM_H2 + (4*rg + i)*65 + k];
                    acc[i][0] = fmaf(a, w0.x, acc[i][0]);
                    acc[i][1] = fmaf(a, w0.y, acc[i][1]);
                    acc[i][2] = fmaf(a, w0.z, acc[i][2]);
                    acc[i][3] = fmaf(a, w0.w, acc[i][3]);
                    acc[i][4] = fmaf(a, w1.x, acc[i][4]);
                    acc[i][5] = fmaf(a, w1.y, acc[i][5]);
                    acc[i][6] = fmaf(a, w1.z, acc[i][6]);
                    acc[i][7] = fmaf(a, w1.w, acc[i][7]);
                }
            }
#pragma unroll
            for (int c = 0; c < 8; c++) {
                float m = fmaxf(acc[0][c], 0.0f);
#pragma unroll
                for (int i = 1; i < 4; i++) m = fmaxf(m, fmaxf(acc[i][c], 0.0f));
                sm[SM_R + rg*128 + 8*cg + c] = m;
            }
        }
        __syncthreads();

        if (tid < 128) {
            float m = sm[SM_R + tid];
#pragma unroll
            for (int r = 1; r < 16; r++) m = fmaxf(m, sm[SM_R + r*128 + tid]);
            dout[(size_t)g * 128 + tid] = m;
        }

        if (ci < 7) gstore(sm + ((ci & 1) ? SM_F0 : SM_F1), e, sub, nv, ndp);
        __syncthreads();
    }
}

// ============================================================================
extern "C" void kernel_launch(void* const* d_in, const int* in_sizes, int n_in,
                              void* d_out, int out_size)
{
    const float* x   = (const float*)d_in[0];
    const float* pos = (const float*)d_in[1];
    const float* W1 = (const float*)d_in[3];
    const float* b1 = (const float*)d_in[4];
    const float* W2 = (const float*)d_in[5];
    const float* b2 = (const float*)d_in[6];
    const float* W3 = (const float*)d_in[7];
    const float* b3 = (const float*)d_in[8];
    float* out = (float*)d_out;

    const int fps_smem = NPTS * 4 * sizeof(float);                 // 64 KB
    const int nbr_smem = fps_smem + 8 * CAP * 2 * sizeof(float);   // 80 KB
    const int mlp_smem = SM_TOT * sizeof(float);                   // ~143.6 KB
    cudaFuncSetAttribute(fps_kernel, cudaFuncAttributeMaxDynamicSharedMemorySize, fps_smem);
    cudaFuncSetAttribute(nbr_kernel, cudaFuncAttributeMaxDynamicSharedMemorySize, nbr_smem);
    cudaFuncSetAttribute(mlp_kernel, cudaFuncAttributeMaxDynamicSharedMemorySize, mlp_smem);

    fps_kernel<<<BATCH, 512, fps_smem>>>(pos, out, out_size);
    nbr_kernel<<<NG / 8, 256, nbr_smem>>>(pos);
    mlp_kernel<<<NG / 8, 256, mlp_smem>>>(x, pos, W1, b1, W2, b2, W3, b3, out, out_size);
}

// round 7
// speedup vs baseline: 2.1254x; 1.3729x over previous
#include <cuda_runtime.h>
#include <cstdint>

#define BATCH 8
#define NPTS  4096
#define MPTS  2048
#define FDIM  64
#define KNBR  64
#define NG    (BATCH*MPTS)
#define CAP   256

// output segments (float32): x_out [NG,128] | pos_out [NG,3] | batch_out [NG]
#define XSEG   (NG*128)
#define PBASE  XSEG
#define BBASE  (XSEG + NG*3)
#define TOTSEG (BBASE + NG)

__device__ float g_q[NG*3];
__device__ int   g_nbr[NG*KNBR];
__device__ int   g_cnt[NG];

typedef unsigned long long u64;

__device__ __forceinline__ unsigned rmax32(unsigned v) {
    unsigned r;
    asm("redux.sync.max.u32 %0, %1, 0xffffffff;" : "=r"(r) : "r"(v));
    return r;
}

__device__ __forceinline__ void cp16(uint32_t dst, const float4* src) {
    asm volatile("cp.async.cg.shared.global [%0], [%1], 16;" :: "r"(dst), "l"(src));
}
#define CP_COMMIT() asm volatile("cp.async.commit_group;" ::: "memory")
#define CP_WAIT0()  asm volatile("cp.async.wait_group 0;"  ::: "memory")

// ============================================================================
// 1) FPS: one block/cloud, 256 threads, 16 pts/thread in registers.
//    Single barrier per step: redux.sync in-warp, packed-u64 cross-warp max.
// ============================================================================
__global__ void __launch_bounds__(256)
fps_kernel(const float* __restrict__ pos, float* __restrict__ dout, int out_size)
{
    extern __shared__ float sp[];              // [NPTS*4]
    __shared__ u64 rd2[16];                    // [parity*8 + warp]

    const int b = blockIdx.x, tid = threadIdx.x;
    const int lane = tid & 31, w = tid >> 5;
    const float* pb = pos + (size_t)b * NPTS * 3;

    for (int i = tid; i < NPTS * 3; i += 256) {
        int p = i / 3, c = i - 3 * p;
        sp[4 * p + c] = pb[i];
    }
    __syncthreads();

    float px[16], py[16], pz[16], md[16];
#pragma unroll
    for (int j = 0; j < 16; j++) {
        int idx = j * 256 + tid;
        px[j] = sp[4 * idx]; py[j] = sp[4 * idx + 1]; pz[j] = sp[4 * idx + 2];
        md[j] = __int_as_float(0x7f800000);
    }

    if (tid == 0) {
        int g = b * MPTS;
        g_q[3*g] = sp[0]; g_q[3*g+1] = sp[1]; g_q[3*g+2] = sp[2];
        if (out_size >= BBASE) {
            dout[PBASE+3*g] = sp[0]; dout[PBASE+3*g+1] = sp[1]; dout[PBASE+3*g+2] = sp[2];
        }
        if (out_size >= TOTSEG) dout[BBASE+g] = (float)b;
    }

    const float4* sp4 = (const float4*)sp;
    int cur = 0;

    for (int step = 1; step < MPTS; step++) {
        float4 L = sp4[cur];
        float bd = -1.0f; int bi = 0;
#pragma unroll
        for (int j = 0; j < 16; j++) {
            float dx = __fadd_rn(px[j], -L.x);
            float dy = __fadd_rn(py[j], -L.y);
            float dz = __fadd_rn(pz[j], -L.z);
            float d  = __fadd_rn(__fadd_rn(__fmul_rn(dx,dx), __fmul_rn(dy,dy)),
                                 __fmul_rn(dz,dz));
            float m = fminf(md[j], d);
            md[j] = m;
            if (m > bd) { bd = m; bi = j * 256 + tid; }
        }
        // warp argmax: max distance bits, then min index among ties
        unsigned dbits = __float_as_uint(bd);            // bd >= 0 -> order-preserving
        unsigned mx   = rmax32(dbits);
        unsigned cand = (dbits == mx) ? (0xFFFFFFFFu - (unsigned)bi) : 0u;
        unsigned cmx  = rmax32(cand);
        if (lane == 0) rd2[(step & 1) * 8 + w] = ((u64)mx << 32) | (u64)cmx;
        __syncthreads();
        const u64* rr = &rd2[(step & 1) * 8];
        u64 best = rr[0];
#pragma unroll
        for (int i = 1; i < 8; i++) { u64 v = rr[i]; if (v > best) best = v; }
        cur = (int)(0xFFFFFFFFu - (unsigned)best);
        if (tid == 0) {
            int g = b * MPTS + step;
            float qx = sp[4*cur], qy = sp[4*cur+1], qz = sp[4*cur+2];
            g_q[3*g] = qx; g_q[3*g+1] = qy; g_q[3*g+2] = qz;
            if (out_size >= BBASE) {
                dout[PBASE+3*g] = qx; dout[PBASE+3*g+1] = qy; dout[PBASE+3*g+2] = qz;
            }
            if (out_size >= TOTSEG) dout[BBASE+g] = (float)b;
        }
        // no second bar: next step's leader stores hit the other parity slot
    }
}

// ============================================================================
// 2) Radius + 64 nearest (stable top_k order). One warp per centroid.
// ============================================================================
__global__ void __launch_bounds__(256)
nbr_kernel(const float* __restrict__ pos)
{
    extern __shared__ float sm2[];             // sp[NPTS*4] | bufd[8*CAP] | bufi[8*CAP]
    float* sp = sm2;
    const int tid = threadIdx.x, lane = tid & 31, w = tid >> 5;
    const int g = blockIdx.x * 8 + w;
    const int b = (blockIdx.x * 8) / MPTS;
    const float* pb = pos + (size_t)b * NPTS * 3;

    for (int i = tid; i < NPTS * 3; i += 256) {
        int p = i / 3, c = i - 3 * p;
        sp[4 * p + c] = pb[i];
    }
    __syncthreads();

    float* bufd = sm2 + 4 * NPTS + w * CAP;
    int*   bufi = (int*)(sm2 + 4 * NPTS + 8 * CAP) + w * CAP;

    const float qx = g_q[3*g], qy = g_q[3*g+1], qz = g_q[3*g+2];
    const float R2 = (float)(0.15 * 0.15);
    const float4* sp4 = (const float4*)sp;

    int cnt = 0;
    for (int i = lane; i < NPTS; i += 32) {
        float4 p = sp4[i];
        float dx = __fadd_rn(qx, -p.x);
        float dy = __fadd_rn(qy, -p.y);
        float dz = __fadd_rn(qz, -p.z);
        float d2 = __fadd_rn(__fadd_rn(__fmul_rn(dx,dx), __fmul_rn(dy,dy)),
                             __fmul_rn(dz,dz));
        bool keep = (d2 <= R2);
        unsigned msk = __ballot_sync(0xffffffffu, keep);
        if (keep) {
            int ofs = cnt + __popc(msk & ((1u << lane) - 1u));
            if (ofs < CAP) { bufd[ofs] = d2; bufi[ofs] = i; }
        }
        cnt += __popc(msk);
    }
    if (cnt > CAP) cnt = CAP;

    if (cnt <= KNBR) {
        for (int t = lane; t < cnt; t += 32) g_nbr[g*KNBR + t] = bufi[t];
        if (lane == 0) g_cnt[g] = cnt;
    } else {
        for (int t = lane; t < cnt; t += 32) {
            float di = bufd[t]; int ii = bufi[t];
            int r = 0;
            for (int j = 0; j < cnt; j++) {
                float dj = bufd[j];
                r += (int)((dj < di) | ((dj == di) & (bufi[j] < ii)));
            }
            if (r < KNBR) g_nbr[g*KNBR + r] = ii;
        }
        if (lane == 0) g_cnt[g] = KNBR;
    }
}

// ============================================================================
// 3) MLP (67->64->64->128, ReLU) + max over neighbors. R3 register tiling;
//    feat gather via cp.async double-buffered across centroids (no registers
//    held through the GEMM body).
// ============================================================================
#define SM_W1 0
#define SM_B1 4288
#define SM_W2 4352
#define SM_B2 8448
#define SM_W3 8512
#define SM_B3 16704
#define SM_F0 16832
#define SM_F1 21184
#define SM_H1 25536
#define SM_H2 29696
#define SM_R  33856
#define SM_TOT 35904

__global__ void __launch_bounds__(256)
mlp_kernel(const float* __restrict__ x, const float* __restrict__ pos,
           const float* __restrict__ W1, const float* __restrict__ b1,
           const float* __restrict__ W2, const float* __restrict__ b2,
           const float* __restrict__ W3, const float* __restrict__ b3,
           float* __restrict__ dout, int out_size)
{
    extern __shared__ float sm[];
    const int tid = threadIdx.x;
    for (int i = tid; i < 4288; i += 256) sm[SM_W1 + i] = W1[i];
    for (int i = tid; i < 4096; i += 256) sm[SM_W2 + i] = W2[i];
    for (int i = tid; i < 8192; i += 256) sm[SM_W3 + i] = W3[i];
    if (tid < 64)  { sm[SM_B1 + tid] = b1[tid]; sm[SM_B2 + tid] = b2[tid]; }
    if (tid < 128)   sm[SM_B3 + tid] = b3[tid];

    const int rg = tid >> 4;    // 0..15: rows 4rg..4rg+3 (neighbors)
    const int cg = tid & 15;    // 0..15: col group
    const int e = tid >> 2, sub = tid & 3;
    const int base = blockIdx.x * 8;

    const uint32_t smF0 = (uint32_t)__cvta_generic_to_shared(sm + SM_F0);
    const uint32_t smF1 = (uint32_t)__cvta_generic_to_shared(sm + SM_F1);
    const uint32_t rowoff = (uint32_t)((e * 68 + sub * 16) * sizeof(float));

    // prologue: gather centroid base+0 into F0
    {
        int cnt = g_cnt[base];
        int je = g_nbr[base * KNBR + e];
        int j0 = g_nbr[base * KNBR];
        int j  = (e < cnt) ? je : j0;
        int bb = base / MPTS;
        const float4* xr = (const float4*)(x + ((size_t)bb * NPTS + j) * FDIM) + sub * 4;
        cp16(smF0 + rowoff +  0, xr + 0);
        cp16(smF0 + rowoff + 16, xr + 1);
        cp16(smF0 + rowoff + 32, xr + 2);
        cp16(smF0 + rowoff + 48, xr + 3);
        CP_COMMIT();
        if (sub == 0) {
            const float* pr = pos + ((size_t)bb * NPTS + j) * 3;
            float dx = __fadd_rn(pr[0], -g_q[3*base]);
            float dy = __fadd_rn(pr[1], -g_q[3*base+1]);
            float dz = __fadd_rn(pr[2], -g_q[3*base+2]);
            CP_WAIT0();
            sm[SM_F0 + e*68 + 64] = dx;
            sm[SM_F0 + e*68 + 65] = dy;
            sm[SM_F0 + e*68 + 66] = dz;
        } else {
            CP_WAIT0();
        }
    }
    __syncthreads();

    for (int ci = 0; ci < 8; ci++) {
        const int g = base + ci;
        const float* feat = sm + ((ci & 1) ? SM_F1 : SM_F0);
        const uint32_t altb = (ci & 1) ? smF0 : smF1;
        float* altf = sm + ((ci & 1) ? SM_F0 : SM_F1);

        // pre-compute next-centroid gather index (loads hide under layer 1)
        int nj = 0, nb = 0;
        if (ci < 7) {
            int cnt = g_cnt[g + 1];
            int je = g_nbr[(g + 1) * KNBR + e];
            int j0 = g_nbr[(g + 1) * KNBR];
            nj = (e < cnt) ? je : j0;
            nb = (g + 1) / MPTS;
        }

        // layer 1: [64x67]@[67x64]
        {
            float acc[4][4];
#pragma unroll
            for (int i = 0; i < 4; i++)
#pragma unroll
                for (int c = 0; c < 4; c++) acc[i][c] = sm[SM_B1 + 4*cg + c];
            for (int k = 0; k < 67; k++) {
                float4 wv = *(const float4*)(sm + SM_W1 + k*64 + 4*cg);
#pragma unroll
                for (int i = 0; i < 4; i++) {
                    float a = feat[(4*rg + i)*68 + k];
                    acc[i][0] = fmaf(a, wv.x, acc[i][0]);
                    acc[i][1] = fmaf(a, wv.y, acc[i][1]);
                    acc[i][2] = fmaf(a, wv.z, acc[i][2]);
                    acc[i][3] = fmaf(a, wv.w, acc[i][3]);
                }
            }
#pragma unroll
            for (int i = 0; i < 4; i++)
#pragma unroll
                for (int c = 0; c < 4; c++)
                    sm[SM_H1 + (4*rg + i)*65 + 4*cg + c] = fmaxf(acc[i][c], 0.0f);
        }
        __syncthreads();

        // issue async gather for next centroid (index already resident)
        float ndx = 0.f, ndy = 0.f, ndz = 0.f;
        if (ci < 7) {
            const float4* xr = (const float4*)(x + ((size_t)nb * NPTS + nj) * FDIM) + sub * 4;
            cp16(altb + rowoff +  0, xr + 0);
            cp16(altb + rowoff + 16, xr + 1);
            cp16(altb + rowoff + 32, xr + 2);
            cp16(altb + rowoff + 48, xr + 3);
            CP_COMMIT();
            if (sub == 0) {
                const float* pr = pos + ((size_t)nb * NPTS + nj) * 3;
                ndx = __fadd_rn(pr[0], -g_q[3*(g+1)]);
                ndy = __fadd_rn(pr[1], -g_q[3*(g+1)+1]);
                ndz = __fadd_rn(pr[2], -g_q[3*(g+1)+2]);
            }
        }

        // layer 2: [64x64]@[64x64]
        {
            float acc[4][4];
#pragma unroll
            for (int i = 0; i < 4; i++)
#pragma unroll
                for (int c = 0; c < 4; c++) acc[i][c] = sm[SM_B2 + 4*cg + c];
            for (int k = 0; k < 64; k++) {
                float4 wv = *(const float4*)(sm + SM_W2 + k*64 + 4*cg);
#pragma unroll
                for (int i = 0; i < 4; i++) {
                    float a = sm[SM_H1 + (4*rg + i)*65 + k];
                    acc[i][0] = fmaf(a, wv.x, acc[i][0]);
                    acc[i][1] = fmaf(a, wv.y, acc[i][1]);
                    acc[i][2] = fmaf(a, wv.z, acc[i][2]);
                    acc[i][3] = fmaf(a, wv.w, acc[i][3]);
                }
            }
#pragma unroll
            for (int i = 0; i < 4; i++)
#pragma unroll
                for (int c = 0; c < 4; c++)
                    sm[SM_H2 + (4*rg + i)*65 + 4*cg + c] = fmaxf(acc[i][c], 0.0f);
        }
        __syncthreads();

        // layer 3: [64x64]@[64x128], relu + max over own 4 rows
        {
            float acc[4][8];
#pragma unroll
            for (int i = 0; i < 4; i++)
#pragma unroll
                for (int c = 0; c < 8; c++) acc[i][c] = sm[SM_B3 + 8*cg + c];
            for (int k = 0; k < 64; k++) {
                float4 w0 = *(const float4*)(sm + SM_W3 + k*128 + 8*cg);
                float4 w1 = *(const float4*)(sm + SM_W3 + k*128 + 8*cg + 4);
#pragma unroll
                for (int i = 0; i < 4; i++) {
                    float a = sm[SM_H2 + (4*rg + i)*65 + k];
                    acc[i][0] = fmaf(a, w0.x, acc[i][0]);
                    acc[i][1] = fmaf(a, w0.y, acc[i][1]);
                    acc[i][2] = fmaf(a, w0.z, acc[i][2]);
                    acc[i][3] = fmaf(a, w0.w, acc[i][3]);
                    acc[i][4] = fmaf(a, w1.x, acc[i][4]);
                    acc[i][5] = fmaf(a, w1.y, acc[i][5]);
                    acc[i][6] = fmaf(a, w1.z, acc[i][6]);
                    acc[i][7] = fmaf(a, w1.w, acc[i][7]);
                }
            }
#pragma unroll
            for (int c = 0; c < 8; c++) {
                float m = fmaxf(acc[0][c], 0.0f);
#pragma unroll
                for (int i = 1; i < 4; i++) m = fmaxf(m, fmaxf(acc[i][c], 0.0f));
                sm[SM_R + rg*128 + 8*cg + c] = m;
            }
        }
        __syncthreads();

        if (tid < 128) {
            float m = sm[SM_R + tid];
#pragma unroll
            for (int r = 1; r < 16; r++) m = fmaxf(m, sm[SM_R + r*128 + tid]);
            dout[(size_t)g * 128 + tid] = m;
        }

        if (ci < 7) {
            CP_WAIT0();
            if (sub == 0) {
                altf[e*68 + 64] = ndx;
                altf[e*68 + 65] = ndy;
                altf[e*68 + 66] = ndz;
            }
        }
        __syncthreads();
    }
}

// ============================================================================
extern "C" void kernel_launch(void* const* d_in, const int* in_sizes, int n_in,
                              void* d_out, int out_size)
{
    const float* x   = (const float*)d_in[0];
    const float* pos = (const float*)d_in[1];
    const float* W1 = (const float*)d_in[3];
    const float* b1 = (const float*)d_in[4];
    const float* W2 = (const float*)d_in[5];
    const float* b2 = (const float*)d_in[6];
    const float* W3 = (const float*)d_in[7];
    const float* b3 = (const float*)d_in[8];
    float* out = (float*)d_out;

    const int fps_smem = NPTS * 4 * sizeof(float);                 // 64 KB
    const int nbr_smem = fps_smem + 8 * CAP * 2 * sizeof(float);   // 80 KB
    const int mlp_smem = SM_TOT * sizeof(float);                   // ~143.6 KB
    cudaFuncSetAttribute(fps_kernel, cudaFuncAttributeMaxDynamicSharedMemorySize, fps_smem);
    cudaFuncSetAttribute(nbr_kernel, cudaFuncAttributeMaxDynamicSharedMemorySize, nbr_smem);
    cudaFuncSetAttribute(mlp_kernel, cudaFuncAttributeMaxDynamicSharedMemorySize, mlp_smem);

    fps_kernel<<<BATCH, 256, fps_smem>>>(pos, out, out_size);
    nbr_kernel<<<NG / 8, 256, nbr_smem>>>(pos);
    mlp_kernel<<<NG / 8, 256, mlp_smem>>>(x, pos, W1, b1, W2, b2, W3, b3, out, out_size);
}

// round 8
// speedup vs baseline: 2.3462x; 1.1039x over previous
#include <cuda_runtime.h>
#include <cstdint>

#define BATCH 8
#define NPTS  4096
#define MPTS  2048
#define FDIM  64
#define KNBR  64
#define NG    (BATCH*MPTS)
#define CAP   256

// output segments (float32): x_out [NG,128] | pos_out [NG,3] | batch_out [NG]
#define XSEG   (NG*128)
#define PBASE  XSEG
#define BBASE  (XSEG + NG*3)
#define TOTSEG (BBASE + NG)

__device__ float g_q[NG*3];
__device__ int   g_nbr[NG*KNBR];
__device__ int   g_cnt[NG];

typedef unsigned long long u64;

__device__ __forceinline__ unsigned rmax32(unsigned v) {
    unsigned r;
    asm("redux.sync.max.u32 %0, %1, 0xffffffff;" : "=r"(r) : "r"(v));
    return r;
}
__device__ __forceinline__ u64 pk2(float lo, float hi) {
    u64 r; asm("mov.b64 %0, {%1, %2};" : "=l"(r) : "f"(lo), "f"(hi)); return r;
}
__device__ __forceinline__ void up2(u64 v, float& lo, float& hi) {
    asm("mov.b64 {%0, %1}, %2;" : "=f"(lo), "=f"(hi) : "l"(v));
}
__device__ __forceinline__ u64 fma2(u64 a, u64 b, u64 c) {
    u64 r; asm("fma.rn.f32x2 %0, %1, %2, %3;" : "=l"(r) : "l"(a), "l"(b), "l"(c)); return r;
}
__device__ __forceinline__ void cp16(uint32_t dst, const float4* src) {
    asm volatile("cp.async.cg.shared.global [%0], [%1], 16;" :: "r"(dst), "l"(src));
}
#define CP_COMMIT() asm volatile("cp.async.commit_group;" ::: "memory")
#define CP_WAIT0()  asm volatile("cp.async.wait_group 0;"  ::: "memory")

// ============================================================================
// 1) FPS (unchanged from proven R6 version)
// ============================================================================
__global__ void __launch_bounds__(256)
fps_kernel(const float* __restrict__ pos, float* __restrict__ dout, int out_size)
{
    extern __shared__ float sp[];              // [NPTS*4]
    __shared__ u64 rd2[16];                    // [parity*8 + warp]

    const int b = blockIdx.x, tid = threadIdx.x;
    const int lane = tid & 31, w = tid >> 5;
    const float* pb = pos + (size_t)b * NPTS * 3;

    for (int i = tid; i < NPTS * 3; i += 256) {
        int p = i / 3, c = i - 3 * p;
        sp[4 * p + c] = pb[i];
    }
    __syncthreads();

    float px[16], py[16], pz[16], md[16];
#pragma unroll
    for (int j = 0; j < 16; j++) {
        int idx = j * 256 + tid;
        px[j] = sp[4 * idx]; py[j] = sp[4 * idx + 1]; pz[j] = sp[4 * idx + 2];
        md[j] = __int_as_float(0x7f800000);
    }

    if (tid == 0) {
        int g = b * MPTS;
        g_q[3*g] = sp[0]; g_q[3*g+1] = sp[1]; g_q[3*g+2] = sp[2];
        if (out_size >= BBASE) {
            dout[PBASE+3*g] = sp[0]; dout[PBASE+3*g+1] = sp[1]; dout[PBASE+3*g+2] = sp[2];
        }
        if (out_size >= TOTSEG) dout[BBASE+g] = (float)b;
    }

    const float4* sp4 = (const float4*)sp;
    int cur = 0;

    for (int step = 1; step < MPTS; step++) {
        float4 L = sp4[cur];
        float bd = -1.0f; int bi = 0;
#pragma unroll
        for (int j = 0; j < 16; j++) {
            float dx = __fadd_rn(px[j], -L.x);
            float dy = __fadd_rn(py[j], -L.y);
            float dz = __fadd_rn(pz[j], -L.z);
            float d  = __fadd_rn(__fadd_rn(__fmul_rn(dx,dx), __fmul_rn(dy,dy)),
                                 __fmul_rn(dz,dz));
            float m = fminf(md[j], d);
            md[j] = m;
            if (m > bd) { bd = m; bi = j * 256 + tid; }
        }
        unsigned dbits = __float_as_uint(bd);
        unsigned mx   = rmax32(dbits);
        unsigned cand = (dbits == mx) ? (0xFFFFFFFFu - (unsigned)bi) : 0u;
        unsigned cmx  = rmax32(cand);
        if (lane == 0) rd2[(step & 1) * 8 + w] = ((u64)mx << 32) | (u64)cmx;
        __syncthreads();
        const u64* rr = &rd2[(step & 1) * 8];
        u64 best = rr[0];
#pragma unroll
        for (int i = 1; i < 8; i++) { u64 v = rr[i]; if (v > best) best = v; }
        cur = (int)(0xFFFFFFFFu - (unsigned)best);
        if (tid == 0) {
            int g = b * MPTS + step;
            float qx = sp[4*cur], qy = sp[4*cur+1], qz = sp[4*cur+2];
            g_q[3*g] = qx; g_q[3*g+1] = qy; g_q[3*g+2] = qz;
            if (out_size >= BBASE) {
                dout[PBASE+3*g] = qx; dout[PBASE+3*g+1] = qy; dout[PBASE+3*g+2] = qz;
            }
            if (out_size >= TOTSEG) dout[BBASE+g] = (float)b;
        }
    }
}

// ============================================================================
// 2) Radius + 64 nearest (unchanged)
// ============================================================================
__global__ void __launch_bounds__(256)
nbr_kernel(const float* __restrict__ pos)
{
    extern __shared__ float sm2[];
    float* sp = sm2;
    const int tid = threadIdx.x, lane = tid & 31, w = tid >> 5;
    const int g = blockIdx.x * 8 + w;
    const int b = (blockIdx.x * 8) / MPTS;
    const float* pb = pos + (size_t)b * NPTS * 3;

    for (int i = tid; i < NPTS * 3; i += 256) {
        int p = i / 3, c = i - 3 * p;
        sp[4 * p + c] = pb[i];
    }
    __syncthreads();

    float* bufd = sm2 + 4 * NPTS + w * CAP;
    int*   bufi = (int*)(sm2 + 4 * NPTS + 8 * CAP) + w * CAP;

    const float qx = g_q[3*g], qy = g_q[3*g+1], qz = g_q[3*g+2];
    const float R2 = (float)(0.15 * 0.15);
    const float4* sp4 = (const float4*)sp;

    int cnt = 0;
    for (int i = lane; i < NPTS; i += 32) {
        float4 p = sp4[i];
        float dx = __fadd_rn(qx, -p.x);
        float dy = __fadd_rn(qy, -p.y);
        float dz = __fadd_rn(qz, -p.z);
        float d2 = __fadd_rn(__fadd_rn(__fmul_rn(dx,dx), __fmul_rn(dy,dy)),
                             __fmul_rn(dz,dz));
        bool keep = (d2 <= R2);
        unsigned msk = __ballot_sync(0xffffffffu, keep);
        if (keep) {
            int ofs = cnt + __popc(msk & ((1u << lane) - 1u));
            if (ofs < CAP) { bufd[ofs] = d2; bufi[ofs] = i; }
        }
        cnt += __popc(msk);
    }
    if (cnt > CAP) cnt = CAP;

    if (cnt <= KNBR) {
        for (int t = lane; t < cnt; t += 32) g_nbr[g*KNBR + t] = bufi[t];
        if (lane == 0) g_cnt[g] = cnt;
    } else {
        for (int t = lane; t < cnt; t += 32) {
            float di = bufd[t]; int ii = bufi[t];
            int r = 0;
            for (int j = 0; j < cnt; j++) {
                float dj = bufd[j];
                r += (int)((dj < di) | ((dj == di) & (bufi[j] < ii)));
            }
            if (r < KNBR) g_nbr[g*KNBR + r] = ii;
        }
        if (lane == 0) g_cnt[g] = KNBR;
    }
}

// ============================================================================
// 3) MLP with f32x2 k-pair packing. Weights transposed in smem (strides 70/66
//    chosen bank-conflict-free for LDS.64 at cols c = cg + 16j).
//    lane-lo accumulates even k, lane-hi odd k; final = lo+hi (reorder OK,
//    tolerance 1e-3). cp.async double-buffered gather retained.
// ============================================================================
#define W1T 0          // 64 x 70 = 4480   W1t[c*70+k] = W1[k*64+c]
#define W2T 4480       // 64 x 66 = 4224
#define W3T 8704       // 128 x 66 = 8448
#define B1O 17152
#define B2O 17216
#define B3O 17280
#define F0O 17408      // 64 x 68 = 4352
#define F1O 21760
#define H1O 26112      // 64 x 66 = 4224
#define H2O 30336
#define RO  34560      // 16 x 128 = 2048
#define SM_TOT 36608

__global__ void __launch_bounds__(256)
mlp_kernel(const float* __restrict__ x, const float* __restrict__ pos,
           const float* __restrict__ W1, const float* __restrict__ b1,
           const float* __restrict__ W2, const float* __restrict__ b2,
           const float* __restrict__ W3, const float* __restrict__ b3,
           float* __restrict__ dout, int out_size)
{
    extern __shared__ float sm[];
    const int tid = threadIdx.x;

    // stage transposed weights + biases
    for (int idx = tid; idx < 67 * 64; idx += 256) {
        int k = idx >> 6, c = idx & 63;
        sm[W1T + c * 70 + k] = W1[idx];
    }
    for (int idx = tid; idx < 64 * 64; idx += 256) {
        int k = idx >> 6, c = idx & 63;
        sm[W2T + c * 66 + k] = W2[idx];
    }
    for (int idx = tid; idx < 64 * 128; idx += 256) {
        int k = idx >> 7, c = idx & 127;
        sm[W3T + c * 66 + k] = W3[idx];
    }
    if (tid < 64)  { sm[B1O + tid] = b1[tid]; sm[B2O + tid] = b2[tid]; }
    if (tid < 128)   sm[B3O + tid] = b3[tid];

    const int rg = tid >> 4;    // 0..15: rows 4rg..4rg+3
    const int cg = tid & 15;    // 0..15
    const int e = tid >> 2, sub = tid & 3;
    const int base = blockIdx.x * 8;

    const uint32_t smF0 = (uint32_t)__cvta_generic_to_shared(sm + F0O);
    const uint32_t smF1 = (uint32_t)__cvta_generic_to_shared(sm + F1O);
    const uint32_t rowoff = (uint32_t)((e * 68 + sub * 16) * sizeof(float));

    // prologue gather into F0
    {
        int cnt = g_cnt[base];
        int je = g_nbr[base * KNBR + e];
        int j0 = g_nbr[base * KNBR];
        int j  = (e < cnt) ? je : j0;
        int bb = base / MPTS;
        const float4* xr = (const float4*)(x + ((size_t)bb * NPTS + j) * FDIM) + sub * 4;
        cp16(smF0 + rowoff +  0, xr + 0);
        cp16(smF0 + rowoff + 16, xr + 1);
        cp16(smF0 + rowoff + 32, xr + 2);
        cp16(smF0 + rowoff + 48, xr + 3);
        CP_COMMIT();
        if (sub == 0) {
            const float* pr = pos + ((size_t)bb * NPTS + j) * 3;
            float dx = __fadd_rn(pr[0], -g_q[3*base]);
            float dy = __fadd_rn(pr[1], -g_q[3*base+1]);
            float dz = __fadd_rn(pr[2], -g_q[3*base+2]);
            CP_WAIT0();
            sm[F0O + e*68 + 64] = dx;
            sm[F0O + e*68 + 65] = dy;
            sm[F0O + e*68 + 66] = dz;
        } else {
            CP_WAIT0();
        }
    }
    __syncthreads();

    for (int ci = 0; ci < 8; ci++) {
        const int g = base + ci;
        const float* feat = sm + ((ci & 1) ? F1O : F0O);
        const uint32_t altb = (ci & 1) ? smF0 : smF1;
        float* altf = sm + ((ci & 1) ? F0O : F1O);

        int nj = 0, nb = 0;
        if (ci < 7) {
            int cnt = g_cnt[g + 1];
            int je = g_nbr[(g + 1) * KNBR + e];
            int j0 = g_nbr[(g + 1) * KNBR];
            nj = (e < cnt) ? je : j0;
            nb = (g + 1) / MPTS;
        }

        // ---- layer 1: K=67 (33 k-pairs + scalar k=66) ----
        {
            u64 acc[4][4];
#pragma unroll
            for (int i = 0; i < 4; i++)
#pragma unroll
                for (int j = 0; j < 4; j++)
                    acc[i][j] = pk2(sm[B1O + cg + 16*j], 0.0f);
            for (int kp = 0; kp < 33; kp++) {
                const int k = 2 * kp;
                u64 a[4];
#pragma unroll
                for (int i = 0; i < 4; i++)
                    a[i] = *(const u64*)(feat + (4*rg + i)*68 + k);
#pragma unroll
                for (int j = 0; j < 4; j++) {
                    u64 wv = *(const u64*)(sm + W1T + (cg + 16*j)*70 + k);
#pragma unroll
                    for (int i = 0; i < 4; i++)
                        acc[i][j] = fma2(a[i], wv, acc[i][j]);
                }
            }
#pragma unroll
            for (int i = 0; i < 4; i++) {
                float a66 = feat[(4*rg + i)*68 + 66];
#pragma unroll
                for (int j = 0; j < 4; j++) {
                    float lo, hi; up2(acc[i][j], lo, hi);
                    float s = __fadd_rn(lo, hi);
                    s = fmaf(a66, sm[W1T + (cg + 16*j)*70 + 66], s);
                    sm[H1O + (4*rg + i)*66 + cg + 16*j] = fmaxf(s, 0.0f);
                }
            }
        }
        __syncthreads();

        // async gather next centroid (hidden under layers 2/3)
        float ndx = 0.f, ndy = 0.f, ndz = 0.f;
        if (ci < 7) {
            const float4* xr = (const float4*)(x + ((size_t)nb * NPTS + nj) * FDIM) + sub * 4;
            cp16(altb + rowoff +  0, xr + 0);
            cp16(altb + rowoff + 16, xr + 1);
            cp16(altb + rowoff + 32, xr + 2);
            cp16(altb + rowoff + 48, xr + 3);
            CP_COMMIT();
            if (sub == 0) {
                const float* pr = pos + ((size_t)nb * NPTS + nj) * 3;
                ndx = __fadd_rn(pr[0], -g_q[3*(g+1)]);
                ndy = __fadd_rn(pr[1], -g_q[3*(g+1)+1]);
                ndz = __fadd_rn(pr[2], -g_q[3*(g+1)+2]);
            }
        }

        // ---- layer 2: K=64 (32 k-pairs) ----
        {
            u64 acc[4][4];
#pragma unroll
            for (int i = 0; i < 4; i++)
#pragma unroll
                for (int j = 0; j < 4; j++)
                    acc[i][j] = pk2(sm[B2O + cg + 16*j], 0.0f);
            for (int kp = 0; kp < 32; kp++) {
                const int k = 2 * kp;
                u64 a[4];
#pragma unroll
                for (int i = 0; i < 4; i++)
                    a[i] = *(const u64*)(sm + H1O + (4*rg + i)*66 + k);
#pragma unroll
                for (int j = 0; j < 4; j++) {
                    u64 wv = *(const u64*)(sm + W2T + (cg + 16*j)*66 + k);
#pragma unroll
                    for (int i = 0; i < 4; i++)
                        acc[i][j] = fma2(a[i], wv, acc[i][j]);
                }
            }
#pragma unroll
            for (int i = 0; i < 4; i++)
#pragma unroll
                for (int j = 0; j < 4; j++) {
                    float lo, hi; up2(acc[i][j], lo, hi);
                    sm[H2O + (4*rg + i)*66 + cg + 16*j] =
                        fmaxf(__fadd_rn(lo, hi), 0.0f);
                }
        }
        __syncthreads();

        // ---- layer 3: K=64, 128 cols (j=0..7), relu + max over 4 rows ----
        {
            u64 acc[4][8];
#pragma unroll
            for (int i = 0; i < 4; i++)
#pragma unroll
                for (int j = 0; j < 8; j++)
                    acc[i][j] = pk2(sm[B3O + cg + 16*j], 0.0f);
            for (int kp = 0; kp < 32; kp++) {
                const int k = 2 * kp;
                u64 a[4];
#pragma unroll
                for (int i = 0; i < 4; i++)
                    a[i] = *(const u64*)(sm + H2O + (4*rg + i)*66 + k);
#pragma unroll
                for (int j = 0; j < 8; j++) {
                    u64 wv = *(const u64*)(sm + W3T + (cg + 16*j)*66 + k);
#pragma unroll
                    for (int i = 0; i < 4; i++)
                        acc[i][j] = fma2(a[i], wv, acc[i][j]);
                }
            }
#pragma unroll
            for (int j = 0; j < 8; j++) {
                float lo, hi; up2(acc[0][j], lo, hi);
                float m = fmaxf(__fadd_rn(lo, hi), 0.0f);
#pragma unroll
                for (int i = 1; i < 4; i++) {
                    up2(acc[i][j], lo, hi);
                    m = fmaxf(m, fmaxf(__fadd_rn(lo, hi), 0.0f));
                }
                sm[RO + rg*128 + cg + 16*j] = m;
            }
        }
        __syncthreads();

        if (tid < 128) {
            float m = sm[RO + tid];
#pragma unroll
            for (int r = 1; r < 16; r++) m = fmaxf(m, sm[RO + r*128 + tid]);
            dout[(size_t)g * 128 + tid] = m;
        }

        if (ci < 7) {
            CP_WAIT0();
            if (sub == 0) {
                altf[e*68 + 64] = ndx;
                altf[e*68 + 65] = ndy;
                altf[e*68 + 66] = ndz;
            }
        }
        __syncthreads();
    }
}

// ============================================================================
extern "C" void kernel_launch(void* const* d_in, const int* in_sizes, int n_in,
                              void* d_out, int out_size)
{
    const float* x   = (const float*)d_in[0];
    const float* pos = (const float*)d_in[1];
    const float* W1 = (const float*)d_in[3];
    const float* b1 = (const float*)d_in[4];
    const float* W2 = (const float*)d_in[5];
    const float* b2 = (const float*)d_in[6];
    const float* W3 = (const float*)d_in[7];
    const float* b3 = (const float*)d_in[8];
    float* out = (float*)d_out;

    const int fps_smem = NPTS * 4 * sizeof(float);                 // 64 KB
    const int nbr_smem = fps_smem + 8 * CAP * 2 * sizeof(float);   // 80 KB
    const int mlp_smem = SM_TOT * sizeof(float);                   // ~143 KB
    cudaFuncSetAttribute(fps_kernel, cudaFuncAttributeMaxDynamicSharedMemorySize, fps_smem);
    cudaFuncSetAttribute(nbr_kernel, cudaFuncAttributeMaxDynamicSharedMemorySize, nbr_smem);
    cudaFuncSetAttribute(mlp_kernel, cudaFuncAttributeMaxDynamicSharedMemorySize, mlp_smem);

    fps_kernel<<<BATCH, 256, fps_smem>>>(pos, out, out_size);
    nbr_kernel<<<NG / 8, 256, nbr_smem>>>(pos);
    mlp_kernel<<<NG / 8, 256, mlp_smem>>>(x, pos, W1, b1, W2, b2, W3, b3, out, out_size);
}

// round 9
// speedup vs baseline: 2.7805x; 1.1851x over previous
#include <cuda_runtime.h>
#include <cstdint>

#define BATCH 8
#define NPTS  4096
#define MPTS  2048
#define FDIM  64
#define KNBR  64
#define NG    (BATCH*MPTS)
#define CAP   256

// output segments (float32): x_out [NG,128] | pos_out [NG,3] | batch_out [NG]
#define XSEG   (NG*128)
#define PBASE  XSEG
#define BBASE  (XSEG + NG*3)
#define TOTSEG (BBASE + NG)

__device__ float  g_q[NG*3];
__device__ float4 g_pos4[BATCH*NPTS];
__device__ volatile int g_prog[BATCH];
__device__ int    g_ctr;

typedef unsigned long long u64;

__device__ __forceinline__ unsigned rmax32(unsigned v) {
    unsigned r;
    asm("redux.sync.max.u32 %0, %1, 0xffffffff;" : "=r"(r) : "r"(v));
    return r;
}
__device__ __forceinline__ u64 pk2(float lo, float hi) {
    u64 r; asm("mov.b64 %0, {%1, %2};" : "=l"(r) : "f"(lo), "f"(hi)); return r;
}
__device__ __forceinline__ void up2(u64 v, float& lo, float& hi) {
    asm("mov.b64 {%0, %1}, %2;" : "=f"(lo), "=f"(hi) : "l"(v));
}
__device__ __forceinline__ u64 fma2(u64 a, u64 b, u64 c) {
    u64 r; asm("fma.rn.f32x2 %0, %1, %2, %3;" : "=l"(r) : "l"(a), "l"(b), "l"(c)); return r;
}
__device__ __forceinline__ void cp16(uint32_t dst, const float4* src) {
    asm volatile("cp.async.cg.shared.global [%0], [%1], 16;" :: "r"(dst), "l"(src));
}
#define CP_COMMIT() asm volatile("cp.async.commit_group;" ::: "memory")
#define CP_WAIT0()  asm volatile("cp.async.wait_group 0;"  ::: "memory")
__device__ __forceinline__ float ldcv(const float* p) {
    float v; asm volatile("ld.global.cv.f32 %0, [%1];" : "=f"(v) : "l"(p)); return v;
}

// ---------------- smem layout (float units) ----------------
#define W1T 0          // 64 x 70
#define W2T 4480       // 64 x 66
#define W3T 8704       // 128 x 66
#define B1O 17152
#define B2O 17216
#define B3O 17280
#define FEAT 17408     // 64 x 68
#define H1O 21760      // 64 x 66
#define H2O 25984      // 64 x 66
#define RO  30208      // 16 x 128
#define CD  32256      // CAP cand d2
#define CI  32512      // CAP cand idx (int)
#define NL  32768      // 64 neighbor idx (int)
#define MS  32832      // [0]=seq [1]=cnt (ints); [4..6]=q (floats)
#define SM_TOT 32840

// ============================================================================
// init: reset counters, build padded float4 pos mirror
// ============================================================================
__global__ void __launch_bounds__(256)
init_kernel(const float* __restrict__ pos)
{
    int i = blockIdx.x * 256 + threadIdx.x;
    if (i == 0) g_ctr = 0;
    if (i < BATCH) g_prog[i] = 0;
    if (i < BATCH * NPTS) {
        const float* p = pos + (size_t)i * 3;
        g_pos4[i] = make_float4(p[0], p[1], p[2], 0.0f);
    }
}

// ============================================================================
// fused persistent kernel: blocks 0..7 produce FPS, then all consume
// ============================================================================
__global__ void __launch_bounds__(256)
fused_kernel(const float* __restrict__ x, const float* __restrict__ pos,
             const float* __restrict__ W1, const float* __restrict__ b1,
             const float* __restrict__ W2, const float* __restrict__ b2,
             const float* __restrict__ W3, const float* __restrict__ b3,
             float* __restrict__ dout, int out_size)
{
    extern __shared__ float sm[];
    const int tid = threadIdx.x;

    // ======================= producer: FPS =======================
    if (blockIdx.x < BATCH) {
        __shared__ u64 rd2[16];
        float* sp = sm;
        const int b = blockIdx.x;
        const int lane = tid & 31, w = tid >> 5;
        const float* pb = pos + (size_t)b * NPTS * 3;

        for (int i = tid; i < NPTS * 3; i += 256) {
            int p = i / 3, c = i - 3 * p;
            sp[4 * p + c] = pb[i];
        }
        __syncthreads();

        float px[16], py[16], pz[16], md[16];
#pragma unroll
        for (int j = 0; j < 16; j++) {
            int idx = j * 256 + tid;
            px[j] = sp[4 * idx]; py[j] = sp[4 * idx + 1]; pz[j] = sp[4 * idx + 2];
            md[j] = __int_as_float(0x7f800000);
        }

        if (tid == 0) {
            int g = b * MPTS;
            g_q[3*g] = sp[0]; g_q[3*g+1] = sp[1]; g_q[3*g+2] = sp[2];
            if (out_size >= BBASE) {
                dout[PBASE+3*g] = sp[0]; dout[PBASE+3*g+1] = sp[1]; dout[PBASE+3*g+2] = sp[2];
            }
            if (out_size >= TOTSEG) dout[BBASE+g] = (float)b;
            __threadfence();
            g_prog[b] = 1;
        }

        const float4* sp4 = (const float4*)sp;
        int cur = 0;

        for (int step = 1; step < MPTS; step++) {
            float4 L = sp4[cur];
            float bd = -1.0f; int bi = 0;
#pragma unroll
            for (int j = 0; j < 16; j++) {
                float dx = __fadd_rn(px[j], -L.x);
                float dy = __fadd_rn(py[j], -L.y);
                float dz = __fadd_rn(pz[j], -L.z);
                float d  = __fadd_rn(__fadd_rn(__fmul_rn(dx,dx), __fmul_rn(dy,dy)),
                                     __fmul_rn(dz,dz));
                float m = fminf(md[j], d);
                md[j] = m;
                if (m > bd) { bd = m; bi = j * 256 + tid; }
            }
            unsigned dbits = __float_as_uint(bd);
            unsigned mx   = rmax32(dbits);
            unsigned cand = (dbits == mx) ? (0xFFFFFFFFu - (unsigned)bi) : 0u;
            unsigned cmx  = rmax32(cand);
            if (lane == 0) rd2[(step & 1) * 8 + w] = ((u64)mx << 32) | (u64)cmx;
            __syncthreads();
            const u64* rr = &rd2[(step & 1) * 8];
            u64 best = rr[0];
#pragma unroll
            for (int i = 1; i < 8; i++) { u64 v = rr[i]; if (v > best) best = v; }
            cur = (int)(0xFFFFFFFFu - (unsigned)best);
            if (tid == 0) {
                int g = b * MPTS + step;
                float qx = sp[4*cur], qy = sp[4*cur+1], qz = sp[4*cur+2];
                g_q[3*g] = qx; g_q[3*g+1] = qy; g_q[3*g+2] = qz;
                if (out_size >= BBASE) {
                    dout[PBASE+3*g] = qx; dout[PBASE+3*g+1] = qy; dout[PBASE+3*g+2] = qz;
                }
                if (out_size >= TOTSEG) dout[BBASE+g] = (float)b;
                __threadfence();
                g_prog[b] = step + 1;
            }
        }
        __syncthreads();
    }

    // ======================= consumer =======================
    // stage transposed weights + biases
    for (int idx = tid; idx < 67 * 64; idx += 256) {
        int k = idx >> 6, c = idx & 63;
        sm[W1T + c * 70 + k] = W1[idx];
    }
    for (int idx = tid; idx < 64 * 64; idx += 256) {
        int k = idx >> 6, c = idx & 63;
        sm[W2T + c * 66 + k] = W2[idx];
    }
    for (int idx = tid; idx < 64 * 128; idx += 256) {
        int k = idx >> 7, c = idx & 127;
        sm[W3T + c * 66 + k] = W3[idx];
    }
    if (tid < 64)  { sm[B1O + tid] = b1[tid]; sm[B2O + tid] = b2[tid]; }
    if (tid < 128)   sm[B3O + tid] = b3[tid];
    __syncthreads();

    int*   msi = (int*)(sm + MS);
    float* msf = sm + MS + 4;
    int*   nl  = (int*)sm + NL;
    int*   ci  = (int*)sm + CI;

    const int rg = tid >> 4;     // 0..15
    const int cg = tid & 15;     // 0..15
    const int e  = tid >> 2, sub = tid & 3;
    const uint32_t smF = (uint32_t)__cvta_generic_to_shared(sm + FEAT);
    const uint32_t rowoff = (uint32_t)((e * 68 + sub * 16) * sizeof(float));
    const float R2 = (float)(0.15 * 0.15);

    for (;;) {
        if (tid == 0) msi[0] = atomicAdd(&g_ctr, 1);
        __syncthreads();
        const int seq = msi[0];
        if (seq >= NG) break;
        const int m = seq >> 3, b = seq & 7;
        const int g = b * MPTS + m;

        if (tid == 0) {
            while (g_prog[b] <= m) __nanosleep(128);
            __threadfence();
            msf[0] = ldcv(&g_q[3*g]);
            msf[1] = ldcv(&g_q[3*g+1]);
            msf[2] = ldcv(&g_q[3*g+2]);
            msi[1] = 0;
        }
        __syncthreads();
        const float qx = msf[0], qy = msf[1], qz = msf[2];

        // ---- neighbor candidates within radius (order-free compaction) ----
        for (int i = tid; i < NPTS; i += 256) {
            float4 p = g_pos4[b * NPTS + i];
            float dx = __fadd_rn(qx, -p.x);
            float dy = __fadd_rn(qy, -p.y);
            float dz = __fadd_rn(qz, -p.z);
            float d2 = __fadd_rn(__fadd_rn(__fmul_rn(dx,dx), __fmul_rn(dy,dy)),
                                 __fmul_rn(dz,dz));
            if (d2 <= R2) {
                int ofs = atomicAdd(&msi[1], 1);
                if (ofs < CAP) { sm[CD + ofs] = d2; ci[ofs] = i; }
            }
        }
        __syncthreads();
        int cnt = msi[1]; if (cnt > CAP) cnt = CAP;

        // ---- rank-select 64 nearest (stable: smaller d2, then lower idx) ----
        if (cnt > KNBR) {
            for (int t = tid; t < cnt; t += 256) {
                float di = sm[CD + t]; int ii = ci[t];
                int r = 0;
                for (int j2 = 0; j2 < cnt; j2++) {
                    float dj = sm[CD + j2];
                    r += (int)((dj < di) | ((dj == di) & (ci[j2] < ii)));
                }
                if (r < KNBR) nl[r] = ii;
            }
        } else {
            for (int t = tid; t < cnt; t += 256) nl[t] = ci[t];
        }
        __syncthreads();
        if (cnt > KNBR) cnt = KNBR;

        // ---- gather feat rows (cp.async from L2-resident x) ----
        {
            int j = nl[(e < cnt) ? e : 0];
            const float4* xr = (const float4*)(x + ((size_t)b * NPTS + j) * FDIM) + sub * 4;
            cp16(smF + rowoff +  0, xr + 0);
            cp16(smF + rowoff + 16, xr + 1);
            cp16(smF + rowoff + 32, xr + 2);
            cp16(smF + rowoff + 48, xr + 3);
            CP_COMMIT();
            if (sub == 0) {
                float4 pr = g_pos4[b * NPTS + j];
                sm[FEAT + e*68 + 64] = __fadd_rn(pr.x, -qx);
                sm[FEAT + e*68 + 65] = __fadd_rn(pr.y, -qy);
                sm[FEAT + e*68 + 66] = __fadd_rn(pr.z, -qz);
            }
            CP_WAIT0();
        }
        __syncthreads();

        // ---- layer 1: K=67 (33 k-pairs + scalar k=66) ----
        {
            u64 acc[4][4];
#pragma unroll
            for (int i = 0; i < 4; i++)
#pragma unroll
                for (int j = 0; j < 4; j++)
                    acc[i][j] = pk2(sm[B1O + cg + 16*j], 0.0f);
            for (int kp = 0; kp < 33; kp++) {
                const int k = 2 * kp;
                u64 a[4];
#pragma unroll
                for (int i = 0; i < 4; i++)
                    a[i] = *(const u64*)(sm + FEAT + (4*rg + i)*68 + k);
#pragma unroll
                for (int j = 0; j < 4; j++) {
                    u64 wv = *(const u64*)(sm + W1T + (cg + 16*j)*70 + k);
#pragma unroll
                    for (int i = 0; i < 4; i++)
                        acc[i][j] = fma2(a[i], wv, acc[i][j]);
                }
            }
#pragma unroll
            for (int i = 0; i < 4; i++) {
                float a66 = sm[FEAT + (4*rg + i)*68 + 66];
#pragma unroll
                for (int j = 0; j < 4; j++) {
                    float lo, hi; up2(acc[i][j], lo, hi);
                    float s = __fadd_rn(lo, hi);
                    s = fmaf(a66, sm[W1T + (cg + 16*j)*70 + 66], s);
                    sm[H1O + (4*rg + i)*66 + cg + 16*j] = fmaxf(s, 0.0f);
                }
            }
        }
        __syncthreads();

        // ---- layer 2: K=64 ----
        {
            u64 acc[4][4];
#pragma unroll
            for (int i = 0; i < 4; i++)
#pragma unroll
                for (int j = 0; j < 4; j++)
                    acc[i][j] = pk2(sm[B2O + cg + 16*j], 0.0f);
            for (int kp = 0; kp < 32; kp++) {
                const int k = 2 * kp;
                u64 a[4];
#pragma unroll
                for (int i = 0; i < 4; i++)
                    a[i] = *(const u64*)(sm + H1O + (4*rg + i)*66 + k);
#pragma unroll
                for (int j = 0; j < 4; j++) {
                    u64 wv = *(const u64*)(sm + W2T + (cg + 16*j)*66 + k);
#pragma unroll
                    for (int i = 0; i < 4; i++)
                        acc[i][j] = fma2(a[i], wv, acc[i][j]);
                }
            }
#pragma unroll
            for (int i = 0; i < 4; i++)
#pragma unroll
                for (int j = 0; j < 4; j++) {
                    float lo, hi; up2(acc[i][j], lo, hi);
                    sm[H2O + (4*rg + i)*66 + cg + 16*j] =
                        fmaxf(__fadd_rn(lo, hi), 0.0f);
                }
        }
        __syncthreads();

        // ---- layer 3: K=64, 128 cols, relu + max over own 4 rows ----
        {
            u64 acc[4][8];
#pragma unroll
            for (int i = 0; i < 4; i++)
#pragma unroll
                for (int j = 0; j < 8; j++)
                    acc[i][j] = pk2(sm[B3O + cg + 16*j], 0.0f);
            for (int kp = 0; kp < 32; kp++) {
                const int k = 2 * kp;
                u64 a[4];
#pragma unroll
                for (int i = 0; i < 4; i++)
                    a[i] = *(const u64*)(sm + H2O + (4*rg + i)*66 + k);
#pragma unroll
                for (int j = 0; j < 8; j++) {
                    u64 wv = *(const u64*)(sm + W3T + (cg + 16*j)*66 + k);
#pragma unroll
                    for (int i = 0; i < 4; i++)
                        acc[i][j] = fma2(a[i], wv, acc[i][j]);
                }
            }
#pragma unroll
            for (int j = 0; j < 8; j++) {
                float lo, hi; up2(acc[0][j], lo, hi);
                float mm = fmaxf(__fadd_rn(lo, hi), 0.0f);
#pragma unroll
                for (int i = 1; i < 4; i++) {
                    up2(acc[i][j], lo, hi);
                    mm = fmaxf(mm, fmaxf(__fadd_rn(lo, hi), 0.0f));
                }
                sm[RO + rg*128 + cg + 16*j] = mm;
            }
        }
        __syncthreads();

        if (tid < 128) {
            float mm = sm[RO + tid];
#pragma unroll
            for (int r = 1; r < 16; r++) mm = fmaxf(mm, sm[RO + r*128 + tid]);
            dout[(size_t)g * 128 + tid] = mm;
        }
        __syncthreads();   // protect smem reuse next iteration
    }
}

// ============================================================================
extern "C" void kernel_launch(void* const* d_in, const int* in_sizes, int n_in,
                              void* d_out, int out_size)
{
    const float* x   = (const float*)d_in[0];
    const float* pos = (const float*)d_in[1];
    const float* W1 = (const float*)d_in[3];
    const float* b1 = (const float*)d_in[4];
    const float* W2 = (const float*)d_in[5];
    const float* b2 = (const float*)d_in[6];
    const float* W3 = (const float*)d_in[7];
    const float* b3 = (const float*)d_in[8];
    float* out = (float*)d_out;

    const int fused_smem = SM_TOT * sizeof(float);   // 131,360 B -> 1 CTA/SM
    cudaFuncSetAttribute(fused_kernel, cudaFuncAttributeMaxDynamicSharedMemorySize,
                         fused_smem);

    init_kernel<<<(BATCH * NPTS + 255) / 256, 256>>>(pos);
    fused_kernel<<<148, 256, fused_smem>>>(x, pos, W1, b1, W2, b2, W3, b3,
                                           out, out_size);
}